// round 9
// baseline (speedup 1.0000x reference)
#include <cuda_runtime.h>
#include <cuda_fp16.h>
#include <math.h>
#include <stdint.h>

// ---------------- problem constants ----------------
#define NTOK 8192
#define DDIM 1024
#define HDIM 4096
#define ODIM 1024
#define NEXP 8
#define TOPK 3

// ---------------- static device scratch ----------------
// g_sync[0..NEXP): per-expert slot counts (gate)
// g_sync[NEXP + e*64 + mtile]: # of GEMM1 n-tile CTAs finished for (e, mtile)
#define NMTILE 64
__device__ int    g_sync[NEXP + NEXP * NMTILE];
__device__ int    g_slot_token[NEXP * NTOK];
__device__ float  g_slot_weight[NEXP * NTOK];
__device__ __half g_h[(size_t)NEXP * NTOK * HDIM];   // 512 MB fp16 h activations

// ---------------- helpers ----------------
__device__ __forceinline__ uint32_t smem_u32(const void* p) {
    uint32_t a;
    asm("{ .reg .u64 t; cvta.to.shared.u64 t, %1; cvt.u32.u64 %0, t; }"
        : "=r"(a) : "l"(p));
    return a;
}

__device__ __forceinline__ uint32_t pack_h2(float lo, float hi) {
    __half2 h = __floats2half2_rn(lo, hi);
    return *reinterpret_cast<uint32_t*>(&h);
}

__device__ __forceinline__ void ldsm_x4(uint32_t addr, uint32_t& r0, uint32_t& r1,
                                        uint32_t& r2, uint32_t& r3) {
    asm volatile("ldmatrix.sync.aligned.m8n8.x4.shared.b16 {%0,%1,%2,%3}, [%4];"
                 : "=r"(r0), "=r"(r1), "=r"(r2), "=r"(r3) : "r"(addr));
}

__device__ __forceinline__ void ldsm_x4_t(uint32_t addr, uint32_t& r0, uint32_t& r1,
                                          uint32_t& r2, uint32_t& r3) {
    asm volatile("ldmatrix.sync.aligned.m8n8.x4.trans.shared.b16 {%0,%1,%2,%3}, [%4];"
                 : "=r"(r0), "=r"(r1), "=r"(r2), "=r"(r3) : "r"(addr));
}

__device__ __forceinline__ void mma_f16(float* d, const uint32_t* a, const uint32_t* b) {
    asm volatile(
        "mma.sync.aligned.m16n8k16.row.col.f32.f16.f16.f32 "
        "{%0,%1,%2,%3}, {%4,%5,%6,%7}, {%8,%9}, {%0,%1,%2,%3};\n"
        : "+f"(d[0]), "+f"(d[1]), "+f"(d[2]), "+f"(d[3])
        : "r"(a[0]), "r"(a[1]), "r"(a[2]), "r"(a[3]),
          "r"(b[0]), "r"(b[1]));
}

// ---------------- fused gate + bucket scatter: one warp per token ----------------
__global__ void gate_kernel(const float* __restrict__ x,
                            const float* __restrict__ gw,
                            const float* __restrict__ gb) {
    int tok  = (blockIdx.x * blockDim.x + threadIdx.x) >> 5;
    int lane = threadIdx.x & 31;
    if (tok >= NTOK) return;

    const float* xr = x + (size_t)tok * DDIM;
    float part[NEXP];
#pragma unroll
    for (int e = 0; e < NEXP; e++) part[e] = 0.0f;

#pragma unroll 4
    for (int j = 0; j < DDIM / 32; j++) {
        int d = j * 32 + lane;
        float xv = xr[d];
        const float4* gp = reinterpret_cast<const float4*>(gw + (size_t)d * NEXP);
        float4 a = gp[0];
        float4 b = gp[1];
        part[0] += xv * a.x; part[1] += xv * a.y;
        part[2] += xv * a.z; part[3] += xv * a.w;
        part[4] += xv * b.x; part[5] += xv * b.y;
        part[6] += xv * b.z; part[7] += xv * b.w;
    }
#pragma unroll
    for (int off = 16; off > 0; off >>= 1)
#pragma unroll
        for (int e = 0; e < NEXP; e++)
            part[e] += __shfl_xor_sync(0xffffffffu, part[e], off);

    if (lane == 0) {
        float s[NEXP];
#pragma unroll
        for (int e = 0; e < NEXP; e++) s[e] = part[e] + gb[e];

        int id[TOPK];
        bool used[NEXP];
#pragma unroll
        for (int e = 0; e < NEXP; e++) used[e] = false;
#pragma unroll
        for (int k = 0; k < TOPK; k++) {
            float best = -1e30f;
            int bi = 0;
#pragma unroll
            for (int e = 0; e < NEXP; e++)
                if (!used[e] && s[e] > best) { best = s[e]; bi = e; }
            used[bi] = true;
            id[k] = bi;
        }

        float mx = s[0];
#pragma unroll
        for (int e = 1; e < NEXP; e++) mx = fmaxf(mx, s[e]);
        float p[NEXP], tot = 0.0f;
#pragma unroll
        for (int e = 0; e < NEXP; e++) { p[e] = expf(s[e] - mx); tot += p[e]; }
        float inv = 1.0f / tot;
        float msum = (p[id[0]] + p[id[1]] + p[id[2]]) * inv;
        float den = msum + 1e-8f;

#pragma unroll
        for (int k = 0; k < TOPK; k++) {
            int e = id[k];
            int pos = atomicAdd(&g_sync[e], 1);
            g_slot_token[e * NTOK + pos]  = tok;
            g_slot_weight[e * NTOK + pos] = (p[e] * inv) / den;
        }
    }
}

// ---------------- fp16 mma.sync GEMM body (shared by both phases) ----------------
#define BM 128
#define BN 128
#define BK 32
#define SA 40     // A row stride (halves)
#define SB 136    // B row stride (halves)
#define A_STAGE_B (BM * SA * 2)              // 10240 bytes
#define B_STAGE_B (BK * SB * 2)              // 8704 bytes
#define STAGE_B (A_STAGE_B + B_STAGE_B)      // 18944 bytes
#define EPI_STRIDE 66
#define SMEM_GEMM_BYTES (4 * 64 * EPI_STRIDE * 4)   // 67584 (> 2*STAGE_B = 37888)

template <int KDIM, int NDIM, bool FIRST, int KSPLIT>
__device__ __forceinline__ void gemm_body(
    const float* __restrict__ A,     // x when FIRST (g_h otherwise)
    const float* __restrict__ B,     // w1 / w2  [E, KDIM, NDIM]
    const float* __restrict__ bias,  // [E, NDIM]
    float* __restrict__ out,
    int e, int m0, int n0, int ks, int cnt,
    char* dsm, int* stok)
{
    const int base = e * NTOK;
    const int kbeg = ks * (KDIM / KSPLIT);
    const uint32_t sb = smem_u32(dsm);

    const int tid  = threadIdx.x;
    const int wid  = tid >> 5;
    const int lane = tid & 31;
    const int gq = lane >> 2;
    const int tg = lane & 3;
    const int wm = wid >> 1;
    const int wn = wid & 1;

    if (FIRST) {
        if (tid < BM) {
            int r = m0 + tid;
            stok[tid] = (r < cnt) ? g_slot_token[base + r] : -1;
        }
    }
    __syncthreads();

    const float*  Apf = A;
    const __half* Aph = g_h;
    const float*  Bp  = B + (size_t)e * KDIM * NDIM;

    const int a_r1 = tid >> 3;
    const int a_c1 = (tid & 7) * 4;
    const int a_r2 = tid >> 2;
    const int a_c2 = (tid & 3) * 8;
    const int b_r  = tid >> 4;
    const int b_c  = (tid & 15) * 4;

    const uint32_t a_lm = (uint32_t)(((wm * 64 + (lane & 15)) * SA + ((lane >> 4) << 3)) * 2);
    const uint32_t b_lm = (uint32_t)(((lane & 15) * SB + wn * 64 + ((lane >> 4) << 3)) * 2);

    float acc[4][8][4];
#pragma unroll
    for (int mi = 0; mi < 4; mi++)
#pragma unroll
        for (int ni = 0; ni < 8; ni++)
#pragma unroll
            for (int r = 0; r < 4; r++) acc[mi][ni][r] = 0.0f;

    float4 la1[8];
    uint4  la2[4];
    float4 lb[4][2];

    auto load_tile = [&](int k0) {
        if (FIRST) {
#pragma unroll
            for (int ro = 0; ro < 8; ro++) {
                int m = ro * 16 + a_r1;
                la1[ro] = make_float4(0.f, 0.f, 0.f, 0.f);
                int tk = stok[m];
                if (tk >= 0)
                    la1[ro] = *reinterpret_cast<const float4*>(
                        Apf + (size_t)tk * KDIM + k0 + a_c1);
            }
        } else {
#pragma unroll
            for (int ro = 0; ro < 4; ro++) {
                int m = ro * 32 + a_r2;
                la2[ro] = make_uint4(0u, 0u, 0u, 0u);
                if (m0 + m < cnt)
                    la2[ro] = *reinterpret_cast<const uint4*>(
                        Aph + (size_t)(base + m0 + m) * KDIM + k0 + a_c2);
            }
        }
#pragma unroll
        for (int ro = 0; ro < 4; ro++) {
            const float* brow = Bp + (size_t)(k0 + ro * 8 + b_r) * NDIM + n0 + b_c;
            lb[ro][0] = *reinterpret_cast<const float4*>(brow);
            lb[ro][1] = *reinterpret_cast<const float4*>(brow + 64);
        }
    };

    auto store_tile = [&](char* stage) {
        __half* As = reinterpret_cast<__half*>(stage);
        __half* Bs = reinterpret_cast<__half*>(stage + A_STAGE_B);
        if (FIRST) {
#pragma unroll
            for (int ro = 0; ro < 8; ro++) {
                int m = ro * 16 + a_r1;
                uint2 u;
                u.x = pack_h2(la1[ro].x, la1[ro].y);
                u.y = pack_h2(la1[ro].z, la1[ro].w);
                *reinterpret_cast<uint2*>(As + m * SA + a_c1) = u;
            }
        } else {
#pragma unroll
            for (int ro = 0; ro < 4; ro++) {
                int m = ro * 32 + a_r2;
                *reinterpret_cast<uint4*>(As + m * SA + a_c2) = la2[ro];
            }
        }
#pragma unroll
        for (int ro = 0; ro < 4; ro++) {
            int kl = ro * 8 + b_r;
#pragma unroll
            for (int h = 0; h < 2; h++) {
                uint2 u;
                u.x = pack_h2(lb[ro][h].x, lb[ro][h].y);
                u.y = pack_h2(lb[ro][h].z, lb[ro][h].w);
                *reinterpret_cast<uint2*>(Bs + kl * SB + h * 64 + b_c) = u;
            }
        }
    };

    // ---- prologue ----
    load_tile(kbeg);
    store_tile(dsm);
    __syncthreads();

    const int KT = (KDIM / KSPLIT) / BK;
    for (int kt = 0; kt < KT; kt++) {
        const int cur = kt & 1;
        const uint32_t a_base = sb + cur * STAGE_B + a_lm;
        const uint32_t b_base = sb + cur * STAGE_B + A_STAGE_B + b_lm;
        const bool more = (kt + 1 < KT);

        if (more) load_tile(kbeg + (kt + 1) * BK);

        uint32_t af[4][4], bf[8][2];

        // ---- kk = 0 chunk ----
#pragma unroll
        for (int mi = 0; mi < 4; mi++)
            ldsm_x4(a_base + (uint32_t)((mi * 16 * SA) * 2),
                    af[mi][0], af[mi][1], af[mi][2], af[mi][3]);
#pragma unroll
        for (int nj = 0; nj < 4; nj++)
            ldsm_x4_t(b_base + (uint32_t)((nj * 16) * 2),
                      bf[2 * nj][0], bf[2 * nj][1], bf[2 * nj + 1][0], bf[2 * nj + 1][1]);
#pragma unroll
        for (int mi = 0; mi < 4; mi++)
#pragma unroll
            for (int ni = 0; ni < 8; ni++)
                mma_f16(acc[mi][ni], af[mi], bf[ni]);

        // ---- kk = 16 chunk: ldmatrix, then STS of next stage, then mma ----
#pragma unroll
        for (int mi = 0; mi < 4; mi++)
            ldsm_x4(a_base + (uint32_t)((mi * 16 * SA + 16) * 2),
                    af[mi][0], af[mi][1], af[mi][2], af[mi][3]);
#pragma unroll
        for (int nj = 0; nj < 4; nj++)
            ldsm_x4_t(b_base + (uint32_t)((16 * SB + nj * 16) * 2),
                      bf[2 * nj][0], bf[2 * nj][1], bf[2 * nj + 1][0], bf[2 * nj + 1][1]);

        if (more) store_tile(dsm + (cur ^ 1) * STAGE_B);

#pragma unroll
        for (int mi = 0; mi < 4; mi++)
#pragma unroll
            for (int ni = 0; ni < 8; ni++)
                mma_f16(acc[mi][ni], af[mi], bf[ni]);

        __syncthreads();
    }

    // ---- epilogue ----
    float* scr = reinterpret_cast<float*>(dsm) + wid * 64 * EPI_STRIDE;
#pragma unroll
    for (int mi = 0; mi < 4; mi++)
#pragma unroll
        for (int ni = 0; ni < 8; ni++)
#pragma unroll
            for (int r = 0; r < 4; r++) {
                int rr = mi * 16 + gq + ((r >= 2) ? 8 : 0);
                int cc = ni * 8 + 2 * tg + (r & 1);
                scr[rr * EPI_STRIDE + cc] = acc[mi][ni][r];
            }
    __syncwarp();

    const int gcol = n0 + wn * 64 + 2 * lane;
    float2 bv = make_float2(0.f, 0.f);
    if (FIRST || ks == 0)
        bv = *reinterpret_cast<const float2*>(bias + (size_t)e * NDIM + gcol);

#pragma unroll 4
    for (int rr = 0; rr < 64; rr++) {
        int slot = m0 + wm * 64 + rr;
        if (slot < cnt) {
            float2 v = *reinterpret_cast<const float2*>(&scr[rr * EPI_STRIDE + 2 * lane]);
            v.x += bv.x; v.y += bv.y;
            if (FIRST) {
                __half2 hv = __floats2half2_rn(fmaxf(v.x, 0.0f), fmaxf(v.y, 0.0f));
                *reinterpret_cast<__half2*>(
                    g_h + (size_t)(base + slot) * NDIM + gcol) = hv;
            } else {
                float wg = g_slot_weight[base + slot];
                int   tk = g_slot_token[base + slot];
                atomicAdd(out + (size_t)tk * NDIM + gcol,     wg * v.x);
                atomicAdd(out + (size_t)tk * NDIM + gcol + 1, wg * v.y);
            }
        }
    }
}

// ---------------- fused both-GEMM kernel with device-side dependencies ----------------
// Grid layout (1-D): [0, G1) = GEMM1 CTAs (dispatched first), [G1, G1+G2) = GEMM2.
// GEMM1 CTA (e, mt, nt) releases done[e*64+mt]; GEMM2 CTA (e, mt, ...) acquires
// done[e*64+mt] == 32 before reading h rows [mt*128, mt*128+128).
#define G1_PER_E ((HDIM / BN) * (NTOK / BM))   // 32*64 = 2048
#define G1_TOTAL (NEXP * G1_PER_E)             // 16384
#define G2_PER_E ((ODIM / BN) * (NTOK / BM) * 2)  // 8*64*2 = 1024
#define G2_TOTAL (NEXP * G2_PER_E)             // 8192

__global__ __launch_bounds__(128, 2) void moe_fused_kernel(
    const float* __restrict__ x,
    const float* __restrict__ w1, const float* __restrict__ b1,
    const float* __restrict__ w2, const float* __restrict__ b2,
    float* __restrict__ out)
{
    extern __shared__ char dsm[];
    __shared__ int stok[BM];
    const int bid = blockIdx.x;
    const int tid = threadIdx.x;

    if (bid < G1_TOTAL) {
        // ---------- GEMM1: h = relu(x @ w1 + b1) ----------
        const int e  = bid >> 11;            // / 2048
        const int r  = bid & 2047;
        const int mt = r >> 5;               // 0..63
        const int nt = r & 31;               // 0..31
        const int cnt = g_sync[e];
        const int m0 = mt * BM;
        if (m0 >= cnt) return;

        gemm_body<DDIM, HDIM, true, 1>(x, w1, b1, nullptr,
                                       e, m0, nt * BN, 0, cnt, dsm, stok);

        // release: all h writes for this (e, mt, nt) visible before count bump
        __threadfence();
        __syncthreads();
        if (tid == 0) atomicAdd(&g_sync[NEXP + e * NMTILE + mt], 1);
    } else {
        // ---------- GEMM2: out += weight * (h @ w2 + b2) ----------
        const int r  = bid - G1_TOTAL;
        const int e  = r >> 10;              // / 1024
        const int r2 = r & 1023;
        const int ks = r2 >> 9;              // 0..1
        const int r3 = r2 & 511;
        const int mt = r3 >> 3;              // 0..63
        const int nt = r3 & 7;               // 0..7
        const int cnt = g_sync[e];
        const int m0 = mt * BM;
        if (m0 >= cnt) return;

        // acquire: wait for all 32 n-tile producers of (e, mt)
        if (tid == 0) {
            int* dp = &g_sync[NEXP + e * NMTILE + mt];
            while (atomicAdd(dp, 0) < (HDIM / BN)) __nanosleep(100);
            __threadfence();
        }
        __syncthreads();

        gemm_body<HDIM, ODIM, false, 2>(nullptr, w2, b2, out,
                                        e, m0, nt * BN, ks, cnt, dsm, stok);
    }
}

// ---------------- launch ----------------
extern "C" void kernel_launch(void* const* d_in, const int* in_sizes, int n_in,
                              void* d_out, int out_size) {
    (void)in_sizes; (void)n_in;
    const float* x  = (const float*)d_in[0];
    const float* gw = (const float*)d_in[1];
    const float* gb = (const float*)d_in[2];
    const float* w1 = (const float*)d_in[3];
    const float* b1 = (const float*)d_in[4];
    const float* w2 = (const float*)d_in[5];
    const float* b2 = (const float*)d_in[6];
    float* out = (float*)d_out;

    static bool ready = false;
    static void* sync_addr = nullptr;
    if (!ready) {
        cudaFuncSetAttribute(moe_fused_kernel,
                             cudaFuncAttributeMaxDynamicSharedMemorySize, SMEM_GEMM_BYTES);
        cudaGetSymbolAddress(&sync_addr, g_sync);
        ready = true;
    }

    cudaMemsetAsync(out, 0, (size_t)out_size * sizeof(float), 0);
    cudaMemsetAsync(sync_addr, 0, sizeof(int) * (NEXP + NEXP * NMTILE), 0);
    gate_kernel<<<NTOK / 8, 256>>>(x, gw, gb);

    moe_fused_kernel<<<G1_TOTAL + G2_TOTAL, 128, SMEM_GEMM_BYTES>>>(
        x, w1, b1, w2, b2, out);
}